// round 15
// baseline (speedup 1.0000x reference)
#include <cuda_runtime.h>
#include <cuda_fp16.h>

#define NMAX 100000
#define EMAX 3200000
#define PEMAX (EMAX + 4 * NMAX)   // padded CSR capacity
#define NG 64
#define NC 10
#define SCANB 1024

// ---------------- device scratch ----------------
__device__ int gcn_degi[NMAX];          // in-degree; zeroed by k_mm1 after last read
__device__ int gcn_off[NMAX + 1];       // padded CSR row offsets (by dst), all %4==0
__device__ int gcn_blocksum[128];
__device__ __align__(16) int gcn_rank[EMAX];   // per-edge within-dst rank (from k_hist)
__device__ __align__(16) int gcn_csrc[PEMAX];  // CSR column (src) indices, padded
__device__ int gcn_batch[NMAX];
__device__ float gcn_dinv[NMAX];
__device__ __align__(16) uint4 gcn_bufA[NMAX + 1];  // [N] sentinel: never written, stays 0
__device__ __align__(16) uint4 gcn_bufB[NMAX + 1];
__device__ float gcn_pool[NG * NC];     // zeroed by k_out after read
__device__ float gcn_cnt[NG];

__device__ __forceinline__ uint4 pack6(const float* o) {
    uint4 r;
    __half2 h01 = __floats2half2_rn(o[0], o[1]);
    __half2 h23 = __floats2half2_rn(o[2], o[3]);
    __half2 h45 = __floats2half2_rn(o[4], o[5]);
    r.x = *(unsigned*)&h01;
    r.y = *(unsigned*)&h23;
    r.z = *(unsigned*)&h45;
    r.w = 0u;
    return r;
}

__device__ __forceinline__ void unpack_add(uint4 v, float* a) {
    float2 f0 = __half22float2(*(__half2*)&v.x);
    float2 f1 = __half22float2(*(__half2*)&v.y);
    float2 f2 = __half22float2(*(__half2*)&v.z);
    a[0] += f0.x; a[1] += f0.y; a[2] += f1.x; a[3] += f1.y; a[4] += f2.x; a[5] += f2.y;
}

// Per-block int64-vs-int32 index detection (first 128 entries, L2-hot).
__device__ __forceinline__ int detect_is64(const void* edge, int N) {
    __shared__ int s_is64;
    if (threadIdx.x < 32) {
        const long long* p = (const long long*)edge;
        int bad = 0;
        for (int t = threadIdx.x; t < 128; t += 32) {
            long long v = p[t];
            if (v < 0 || v >= (long long)N) bad = 1;
        }
        bad = __any_sync(0xffffffffu, bad);
        if (threadIdx.x == 0) s_is64 = bad ? 0 : 1;
    }
    __syncthreads();
    return s_is64;
}

// Load 4 ints starting at edge index e0 (e0 % 4 == 0) from int32 or int64 array.
__device__ __forceinline__ int4 load4idx(const void* base, size_t off4, int is64) {
    if (is64) {
        const longlong2* p = (const longlong2*)base;
        longlong2 a = __ldg(&p[off4 * 2]);
        longlong2 b = __ldg(&p[off4 * 2 + 1]);
        return make_int4((int)a.x, (int)a.y, (int)b.x, (int)b.y);
    }
    return __ldg(&((const int4*)base)[off4]);
}

// Pack-padded CSR walk, 4 threads/node, double-pack unroll.
__device__ __forceinline__ void row_accum(const uint4* __restrict__ vin,
                                          int pbase, int pend, int q, float* a) {
#pragma unroll
    for (int j = 0; j < 6; j++) a[j] = 0.0f;
    const int4* cp = (const int4*)gcn_csrc;
    int p = pbase + q;
#pragma unroll 1
    for (; p + 4 < pend; p += 8) {
        int4 s0 = __ldg(&cp[p]);
        int4 s1 = __ldg(&cp[p + 4]);
        uint4 v0 = __ldg(&vin[s0.x]);
        uint4 v1 = __ldg(&vin[s0.y]);
        uint4 v2 = __ldg(&vin[s0.z]);
        uint4 v3 = __ldg(&vin[s0.w]);
        uint4 v4 = __ldg(&vin[s1.x]);
        uint4 v5 = __ldg(&vin[s1.y]);
        uint4 v6 = __ldg(&vin[s1.z]);
        uint4 v7 = __ldg(&vin[s1.w]);
        unpack_add(v0, a); unpack_add(v1, a); unpack_add(v2, a); unpack_add(v3, a);
        unpack_add(v4, a); unpack_add(v5, a); unpack_add(v6, a); unpack_add(v7, a);
    }
    if (p < pend) {
        int4 s = __ldg(&cp[p]);
        uint4 v0 = __ldg(&vin[s.x]);
        uint4 v1 = __ldg(&vin[s.y]);
        uint4 v2 = __ldg(&vin[s.z]);
        uint4 v3 = __ldg(&vin[s.w]);
        unpack_add(v0, a); unpack_add(v1, a); unpack_add(v2, a); unpack_add(v3, a);
    }
}

// ------ degree histogram + per-edge rank capture + batch counts -------------
__global__ __launch_bounds__(256) void k_hist(const void* edge, const void* batchp,
                                              int N, int E) {
    int is64 = detect_is64(edge, N);
    int i = blockIdx.x * 256 + threadIdx.x;
    int i4 = i * 4;
    const void* dbase = is64 ? (const void*)((const long long*)edge + E)
                             : (const void*)((const int*)edge + E);
    if (i4 + 3 < E) {
        int4 d = load4idx(dbase, i, is64);
        int4 r;
        r.x = atomicAdd(&gcn_degi[d.x], 1);
        r.y = atomicAdd(&gcn_degi[d.y], 1);
        r.z = atomicAdd(&gcn_degi[d.z], 1);
        r.w = atomicAdd(&gcn_degi[d.w], 1);
        ((int4*)gcn_rank)[i] = r;            // coalesced rank store
    } else {
        for (int e = i4; e < E; e++) {
            int d = is64 ? (int)((const long long*)edge)[(size_t)E + e]
                         : ((const int*)edge)[(size_t)E + e];
            gcn_rank[e] = atomicAdd(&gcn_degi[d], 1);
        }
    }
    if (i < N) {
        int b = is64 ? (int)((const long long*)batchp)[i] : ((const int*)batchp)[i];
        gcn_batch[i] = b;
        atomicAdd(&gcn_cnt[b], 1.0f);
    }
}

// -------- scan phase 1: per-block exclusive scan of PADDED degree ----------
__global__ __launch_bounds__(SCANB) void k_scan1(int N) {
    __shared__ int s[SCANB];
    int t = threadIdx.x;
    int i = blockIdx.x * SCANB + t;
    int v = (i < N) ? ((gcn_degi[i] + 3) & ~3) : 0;
    s[t] = v;
    __syncthreads();
    for (int d = 1; d < SCANB; d <<= 1) {
        int x = (t >= d) ? s[t - d] : 0;
        __syncthreads();
        s[t] += x;
        __syncthreads();
    }
    if (i < N) gcn_off[i] = s[t] - v;
    if (t == SCANB - 1) gcn_blocksum[blockIdx.x] = s[t];
}

// -------- scan phase 2+3 fused (+ row padding), 128-thread blocks ----------
__global__ __launch_bounds__(128) void k_scan3(int N, int nblk) {
    __shared__ int bs[128];
    int t = threadIdx.x;
    int v = (t < nblk) ? gcn_blocksum[t] : 0;
    bs[t] = v;
    __syncthreads();
    for (int d = 1; d < 128; d <<= 1) {
        int x = (t >= d) ? bs[t - d] : 0;
        __syncthreads();
        bs[t] += x;
        __syncthreads();
    }
    int i = blockIdx.x * 128 + t;
    if (i < N) {
        int blk = i >> 10;
        int base = (blk == 0) ? 0 : bs[blk - 1];
        int o = gcn_off[i] + base;
        gcn_off[i] = o;
        int deg = gcn_degi[i];
        int pdeg = (deg + 3) & ~3;
        for (int e = o + deg; e < o + pdeg; e++) gcn_csrc[e] = N;  // sentinel pad
        if (i == N - 1) gcn_off[N] = o + pdeg;
    }
}

// --------- CSR fill: ATOMIC-FREE scatter, 8 edges/thread (deep MLP) ---------
__global__ __launch_bounds__(256) void k_fill(const void* edge, int N, int E) {
    int is64 = detect_is64(edge, N);
    int i = blockIdx.x * 256 + threadIdx.x;
    int e0 = i * 8;
    const void* dbase = is64 ? (const void*)((const long long*)edge + E)
                             : (const void*)((const int*)edge + E);
    if (e0 + 7 < E) {
        int4 sa = load4idx(edge, 2 * i, is64);
        int4 sb = load4idx(edge, 2 * i + 1, is64);
        int4 da = load4idx(dbase, 2 * i, is64);
        int4 db = load4idx(dbase, 2 * i + 1, is64);
        int4 ra = ((const int4*)gcn_rank)[2 * i];
        int4 rb = ((const int4*)gcn_rank)[2 * i + 1];
        int o0 = __ldg(&gcn_off[da.x]);
        int o1 = __ldg(&gcn_off[da.y]);
        int o2 = __ldg(&gcn_off[da.z]);
        int o3 = __ldg(&gcn_off[da.w]);
        int o4 = __ldg(&gcn_off[db.x]);
        int o5 = __ldg(&gcn_off[db.y]);
        int o6 = __ldg(&gcn_off[db.z]);
        int o7 = __ldg(&gcn_off[db.w]);
        gcn_csrc[o0 + ra.x] = sa.x;
        gcn_csrc[o1 + ra.y] = sa.y;
        gcn_csrc[o2 + ra.z] = sa.z;
        gcn_csrc[o3 + ra.w] = sa.w;
        gcn_csrc[o4 + rb.x] = sb.x;
        gcn_csrc[o5 + rb.y] = sb.y;
        gcn_csrc[o6 + rb.z] = sb.z;
        gcn_csrc[o7 + rb.w] = sb.w;
    } else {
        for (int e = e0; e < E; e++) {
            int s, d;
            if (is64) {
                s = (int)((const long long*)edge)[e];
                d = (int)((const long long*)edge)[(size_t)E + e];
            } else {
                s = ((const int*)edge)[e];
                d = ((const int*)edge)[(size_t)E + e];
            }
            gcn_csrc[__ldg(&gcn_off[d]) + gcn_rank[e]] = s;
        }
    }
}

// ---------------- layer-1 transform (4 lanes/row, 128-thr blocks) -----------
__global__ __launch_bounds__(128) void k_mm1(const float* __restrict__ x,
                                             const float* __restrict__ W, int N) {
    __shared__ float sW[128 * 8];
    for (int t = threadIdx.x; t < 1024; t += 128) {
        int k = t >> 3, j = t & 7;
        sW[t] = (j < 6) ? W[k * 6 + j] : 0.0f;
    }
    __syncthreads();
    int g = blockIdx.x * 128 + threadIdx.x;
    int i = g >> 2;
    int q = g & 3;
    if (i >= N) return;
    const float4* xr = (const float4*)(x + (size_t)i * 128) + q * 8;
    float a[6];
#pragma unroll
    for (int j = 0; j < 6; j++) a[j] = 0.0f;
#pragma unroll
    for (int k4 = 0; k4 < 8; k4++) {
        float4 xv = xr[k4];
        const float* wp = &sW[(q * 8 + k4) * 32];
#pragma unroll
        for (int j = 0; j < 6; j++) {
            a[j] += xv.x * wp[j] + xv.y * wp[8 + j] + xv.z * wp[16 + j] + xv.w * wp[24 + j];
        }
    }
#pragma unroll
    for (int j = 0; j < 6; j++) {
        a[j] += __shfl_xor_sync(0xffffffffu, a[j], 1);
        a[j] += __shfl_xor_sync(0xffffffffu, a[j], 2);
    }
    if (q == 0) {
        float dinv = rsqrtf((float)(gcn_degi[i] + 1));   // +1: self loop
        gcn_degi[i] = 0;                                 // self-clean for next replay
        gcn_dinv[i] = dinv;
        float o[6] = { a[0] * dinv, a[1] * dinv, a[2] * dinv,
                       a[3] * dinv, a[4] * dinv, a[5] * dinv };
        gcn_bufA[i] = pack6(o);
    }
}

// --- fused CSR aggregation (4 threads/node, 128-thr blocks) + epilogue ------
template <bool APPLY_W>
__global__ __launch_bounds__(128) void k_csr(const uint4* __restrict__ vin,
                                             uint4* __restrict__ vout,
                                             const float* __restrict__ b,
                                             const float* __restrict__ W, int N) {
    __shared__ float sW[48];
    __shared__ float sb[6];
    if (threadIdx.x < 48) {
        int k = threadIdx.x >> 3, j = threadIdx.x & 7;
        sW[threadIdx.x] = (APPLY_W && j < 6) ? W[k * 6 + j] : 0.0f;
    }
    if (threadIdx.x < 6) sb[threadIdx.x] = b[threadIdx.x];
    __syncthreads();
    int g = blockIdx.x * 128 + threadIdx.x;
    int i = g >> 2;
    int q = g & 3;
    bool valid = (i < N);
    int pbase = 0, pend = 0;
    if (valid) { pbase = gcn_off[i] >> 2; pend = gcn_off[i + 1] >> 2; }

    float a[6];
    row_accum(vin, pbase, pend, q, a);

#pragma unroll
    for (int j = 0; j < 6; j++) {
        a[j] += __shfl_xor_sync(0xffffffffu, a[j], 1);
        a[j] += __shfl_xor_sync(0xffffffffu, a[j], 2);
    }
    if (!valid || q != 0) return;

    unpack_add(__ldg(&vin[i]), a);       // self loop
    float dinv = gcn_dinv[i];
    float h[6];
#pragma unroll
    for (int j = 0; j < 6; j++) h[j] = fmaxf(dinv * a[j] + sb[j], 0.0f);
    float o[6];
    if (APPLY_W) {
#pragma unroll
        for (int j = 0; j < 6; j++) {
            float s = 0.0f;
#pragma unroll
            for (int k = 0; k < 6; k++) s += h[k] * sW[k * 8 + j];
            o[j] = s * dinv;
        }
    } else {
#pragma unroll
        for (int j = 0; j < 6; j++) o[j] = h[j] * dinv;
    }
    vout[i] = pack6(o);
}

// ---------------- final: CSR agg (4t/node) + (agg @ Wf + bf) relu + pool ----
__global__ __launch_bounds__(128) void k_csr_final(const uint4* __restrict__ vin,
                                                   const float* __restrict__ Wf,
                                                   const float* __restrict__ bf, int N) {
    __shared__ float sW[60];
    __shared__ float sb[10];
    __shared__ float sp[NG * NC];
    for (int t = threadIdx.x; t < NG * NC; t += 128) sp[t] = 0.0f;
    if (threadIdx.x < 60) sW[threadIdx.x] = Wf[threadIdx.x];
    if (threadIdx.x < 10) sb[threadIdx.x] = bf[threadIdx.x];
    __syncthreads();
    int g = blockIdx.x * 128 + threadIdx.x;
    int i = g >> 2;
    int q = g & 3;
    bool valid = (i < N);
    int pbase = 0, pend = 0;
    if (valid) { pbase = gcn_off[i] >> 2; pend = gcn_off[i + 1] >> 2; }

    float a[6];
    row_accum(vin, pbase, pend, q, a);
#pragma unroll
    for (int j = 0; j < 6; j++) {
        a[j] += __shfl_xor_sync(0xffffffffu, a[j], 1);
        a[j] += __shfl_xor_sync(0xffffffffu, a[j], 2);
    }
    if (valid && q == 0) {
        unpack_add(__ldg(&vin[i]), a);
        float dinv = gcn_dinv[i];
#pragma unroll
        for (int j = 0; j < 6; j++) a[j] *= dinv;
        int bg = gcn_batch[i];
#pragma unroll
        for (int c = 0; c < 10; c++) {
            float s = sb[c];
#pragma unroll
            for (int j = 0; j < 6; j++) s += a[j] * sW[j * 10 + c];
            s = fmaxf(s, 0.0f);
            atomicAdd(&sp[bg * 10 + c], s);
        }
    }
    __syncthreads();
    int first = blockIdx.x * 32;           // 32 nodes per block (4 threads each)
    if (first >= N) return;
    int last = min(first + 31, N - 1);
    int bmin = gcn_batch[first], bmax = gcn_batch[last];   // batch sorted
    int cnt = (bmax - bmin + 1) * 10;
    for (int t = threadIdx.x; t < cnt; t += 128) {
        float v = sp[bmin * 10 + t];
        if (v != 0.0f) atomicAdd(&gcn_pool[bmin * 10 + t], v);
    }
}

// ------- mean + log_softmax; self-cleans pool/cnt for the next replay -------
__global__ void k_out(float* __restrict__ out) {
    int g = threadIdx.x;
    if (g < NG) {
        float cnt = fmaxf(gcn_cnt[g], 1.0f);
        float p[10];
        float m = -1e30f;
#pragma unroll
        for (int c = 0; c < 10; c++) {
            p[c] = gcn_pool[g * 10 + c] / cnt;
            m = fmaxf(m, p[c]);
        }
        float s = 0.0f;
#pragma unroll
        for (int c = 0; c < 10; c++) s += expf(p[c] - m);
        float l = logf(s);
#pragma unroll
        for (int c = 0; c < 10; c++) out[g * 10 + c] = p[c] - m - l;
    }
    __syncthreads();
    if (threadIdx.x < NG * NC) gcn_pool[threadIdx.x] = 0.0f;   // self-clean
    if (threadIdx.x < NG) gcn_cnt[threadIdx.x] = 0.0f;
}

// ---------------- launch ----------------
extern "C" void kernel_launch(void* const* d_in, const int* in_sizes, int n_in,
                              void* d_out, int out_size) {
    const float* x     = (const float*)d_in[0];
    const void*  edge  = d_in[1];
    const void*  batch = d_in[2];
    const float* W1 = (const float*)d_in[3];
    const float* b1 = (const float*)d_in[4];
    const float* W2 = (const float*)d_in[5];
    const float* b2 = (const float*)d_in[6];
    const float* W3 = (const float*)d_in[7];
    const float* b3 = (const float*)d_in[8];
    const float* W4 = (const float*)d_in[9];
    const float* b4 = (const float*)d_in[10];
    const float* W5 = (const float*)d_in[11];
    const float* b5 = (const float*)d_in[12];
    const float* W6 = (const float*)d_in[13];
    const float* b6 = (const float*)d_in[14];
    const float* Wf = (const float*)d_in[15];
    const float* bf = (const float*)d_in[16];

    int N = in_sizes[0] / 128;
    int E = in_sizes[1] / 2;
    float* out = (float*)d_out;

    int nb_n2 = (N + 127) / 128;
    int nb_e4 = ((E + 3) / 4 + 255) / 256;
    int nb_e8 = ((E + 7) / 8 + 255) / 256;
    int nb_s  = (N + SCANB - 1) / SCANB;
    int nb_m4 = (4 * N + 127) / 128;   // 4 threads per node, 128-thr blocks

    void* pA; void* pB;
    cudaGetSymbolAddress(&pA, gcn_bufA);
    cudaGetSymbolAddress(&pB, gcn_bufB);
    uint4* A  = (uint4*)pA;
    uint4* Bv = (uint4*)pB;

    k_hist<<<nb_e4, 256>>>(edge, batch, N, E);
    k_scan1<<<nb_s, SCANB>>>(N);
    k_scan3<<<nb_n2, 128>>>(N, nb_s);   // fused scan2 + scan3 + pad
    k_fill<<<nb_e8, 256>>>(edge, N, E); // atomic-free scatter, 8 edges/thread

    k_mm1<<<nb_m4, 128>>>(x, W1, N);                        // -> A (g1); cleans degi
    k_csr<true><<<nb_m4, 128>>>(A, Bv, b1, W2, N);          // -> B (g2)
    k_csr<true><<<nb_m4, 128>>>(Bv, A, b2, W3, N);          // -> A (g3)
    k_csr<true><<<nb_m4, 128>>>(A, Bv, b3, W4, N);          // -> B (g4)
    k_csr<true><<<nb_m4, 128>>>(Bv, A, b4, W5, N);          // -> A (g5)
    k_csr<true><<<nb_m4, 128>>>(A, Bv, b5, W6, N);          // -> B (g6)
    k_csr<false><<<nb_m4, 128>>>(Bv, A, b6, nullptr, N);    // -> A (h6*dinv)
    k_csr_final<<<nb_m4, 128>>>(A, Wf, bf, N);
    k_out<<<1, NG * NC>>>(out);                             // cleans pool/cnt
}

// round 16
// speedup vs baseline: 1.0064x; 1.0064x over previous
#include <cuda_runtime.h>
#include <cuda_fp16.h>

#define NMAX 100000
#define EMAX 3200000
#define PEMAX (EMAX + 4 * NMAX)   // padded CSR capacity
#define NG 64
#define NC 10
#define SCANB 1024

// ---------------- device scratch ----------------
__device__ int gcn_degi[NMAX];          // in-degree; zeroed by k_mm1 after last read
__device__ int gcn_off[NMAX + 1];       // padded CSR row offsets (by dst), all %4==0
__device__ int gcn_blocksum[128];
__device__ __align__(16) int gcn_rank[EMAX];   // per-edge within-dst rank (from k_hist)
__device__ __align__(16) int gcn_csrc[PEMAX];  // CSR column (src) indices, padded
__device__ int gcn_batch[NMAX];
__device__ float gcn_dinv[NMAX];
__device__ __align__(16) uint4 gcn_bufA[NMAX + 1];  // [N] sentinel: never written, stays 0
__device__ __align__(16) uint4 gcn_bufB[NMAX + 1];
__device__ float gcn_pool[NG * NC];     // zeroed by k_out after read
__device__ float gcn_cnt[NG];

__device__ __forceinline__ uint4 pack6(const float* o) {
    uint4 r;
    __half2 h01 = __floats2half2_rn(o[0], o[1]);
    __half2 h23 = __floats2half2_rn(o[2], o[3]);
    __half2 h45 = __floats2half2_rn(o[4], o[5]);
    r.x = *(unsigned*)&h01;
    r.y = *(unsigned*)&h23;
    r.z = *(unsigned*)&h45;
    r.w = 0u;
    return r;
}

__device__ __forceinline__ void unpack_add(uint4 v, float* a) {
    float2 f0 = __half22float2(*(__half2*)&v.x);
    float2 f1 = __half22float2(*(__half2*)&v.y);
    float2 f2 = __half22float2(*(__half2*)&v.z);
    a[0] += f0.x; a[1] += f0.y; a[2] += f1.x; a[3] += f1.y; a[4] += f2.x; a[5] += f2.y;
}

// Per-block int64-vs-int32 index detection (first 128 entries, L2-hot).
__device__ __forceinline__ int detect_is64(const void* edge, int N) {
    __shared__ int s_is64;
    if (threadIdx.x < 32) {
        const long long* p = (const long long*)edge;
        int bad = 0;
        for (int t = threadIdx.x; t < 128; t += 32) {
            long long v = p[t];
            if (v < 0 || v >= (long long)N) bad = 1;
        }
        bad = __any_sync(0xffffffffu, bad);
        if (threadIdx.x == 0) s_is64 = bad ? 0 : 1;
    }
    __syncthreads();
    return s_is64;
}

// Load 4 ints at pack index off4 from int32 or int64 array.
__device__ __forceinline__ int4 load4idx(const void* base, size_t off4, int is64) {
    if (is64) {
        const longlong2* p = (const longlong2*)base;
        longlong2 a = __ldg(&p[off4 * 2]);
        longlong2 b = __ldg(&p[off4 * 2 + 1]);
        return make_int4((int)a.x, (int)a.y, (int)b.x, (int)b.y);
    }
    return __ldg(&((const int4*)base)[off4]);
}

// Pack-padded CSR walk, 4 threads/node, double-pack unroll.
__device__ __forceinline__ void row_accum(const uint4* __restrict__ vin,
                                          int pbase, int pend, int q, float* a) {
#pragma unroll
    for (int j = 0; j < 6; j++) a[j] = 0.0f;
    const int4* cp = (const int4*)gcn_csrc;
    int p = pbase + q;
#pragma unroll 1
    for (; p + 4 < pend; p += 8) {
        int4 s0 = __ldg(&cp[p]);
        int4 s1 = __ldg(&cp[p + 4]);
        uint4 v0 = __ldg(&vin[s0.x]);
        uint4 v1 = __ldg(&vin[s0.y]);
        uint4 v2 = __ldg(&vin[s0.z]);
        uint4 v3 = __ldg(&vin[s0.w]);
        uint4 v4 = __ldg(&vin[s1.x]);
        uint4 v5 = __ldg(&vin[s1.y]);
        uint4 v6 = __ldg(&vin[s1.z]);
        uint4 v7 = __ldg(&vin[s1.w]);
        unpack_add(v0, a); unpack_add(v1, a); unpack_add(v2, a); unpack_add(v3, a);
        unpack_add(v4, a); unpack_add(v5, a); unpack_add(v6, a); unpack_add(v7, a);
    }
    if (p < pend) {
        int4 s = __ldg(&cp[p]);
        uint4 v0 = __ldg(&vin[s.x]);
        uint4 v1 = __ldg(&vin[s.y]);
        uint4 v2 = __ldg(&vin[s.z]);
        uint4 v3 = __ldg(&vin[s.w]);
        unpack_add(v0, a); unpack_add(v1, a); unpack_add(v2, a); unpack_add(v3, a);
    }
}

// ------ degree histogram + per-edge rank capture + batch counts -------------
__global__ __launch_bounds__(256) void k_hist(const void* edge, const void* batchp,
                                              int N, int E) {
    int is64 = detect_is64(edge, N);
    int i = blockIdx.x * 256 + threadIdx.x;
    int i4 = i * 4;
    const void* dbase = is64 ? (const void*)((const long long*)edge + E)
                             : (const void*)((const int*)edge + E);
    if (i4 + 3 < E) {
        int4 d = load4idx(dbase, i, is64);
        int4 r;
        r.x = atomicAdd(&gcn_degi[d.x], 1);
        r.y = atomicAdd(&gcn_degi[d.y], 1);
        r.z = atomicAdd(&gcn_degi[d.z], 1);
        r.w = atomicAdd(&gcn_degi[d.w], 1);
        ((int4*)gcn_rank)[i] = r;            // coalesced rank store
    } else {
        for (int e = i4; e < E; e++) {
            int d = is64 ? (int)((const long long*)edge)[(size_t)E + e]
                         : ((const int*)edge)[(size_t)E + e];
            gcn_rank[e] = atomicAdd(&gcn_degi[d], 1);
        }
    }
    if (i < N) {
        int b = is64 ? (int)((const long long*)batchp)[i] : ((const int*)batchp)[i];
        gcn_batch[i] = b;
        atomicAdd(&gcn_cnt[b], 1.0f);
    }
}

// -------- scan phase 1: per-block exclusive scan of PADDED degree ----------
__global__ __launch_bounds__(SCANB) void k_scan1(int N) {
    __shared__ int s[SCANB];
    int t = threadIdx.x;
    int i = blockIdx.x * SCANB + t;
    int v = (i < N) ? ((gcn_degi[i] + 3) & ~3) : 0;
    s[t] = v;
    __syncthreads();
    for (int d = 1; d < SCANB; d <<= 1) {
        int x = (t >= d) ? s[t - d] : 0;
        __syncthreads();
        s[t] += x;
        __syncthreads();
    }
    if (i < N) gcn_off[i] = s[t] - v;
    if (t == SCANB - 1) gcn_blocksum[blockIdx.x] = s[t];
}

// -------- scan phase 2+3 fused (+ row padding), 128-thread blocks ----------
__global__ __launch_bounds__(128) void k_scan3(int N, int nblk) {
    __shared__ int bs[128];
    int t = threadIdx.x;
    int v = (t < nblk) ? gcn_blocksum[t] : 0;
    bs[t] = v;
    __syncthreads();
    for (int d = 1; d < 128; d <<= 1) {
        int x = (t >= d) ? bs[t - d] : 0;
        __syncthreads();
        bs[t] += x;
        __syncthreads();
    }
    int i = blockIdx.x * 128 + t;
    if (i < N) {
        int blk = i >> 10;
        int base = (blk == 0) ? 0 : bs[blk - 1];
        int o = gcn_off[i] + base;
        gcn_off[i] = o;
        int deg = gcn_degi[i];
        int pdeg = (deg + 3) & ~3;
        for (int e = o + deg; e < o + pdeg; e++) gcn_csrc[e] = N;  // sentinel pad
        if (i == N - 1) gcn_off[N] = o + pdeg;
    }
}

// --------- CSR fill: ATOMIC-FREE scatter, 4 edges/thread (R14 config) -------
__global__ __launch_bounds__(256) void k_fill(const void* edge, int N, int E) {
    int is64 = detect_is64(edge, N);
    int i = blockIdx.x * 256 + threadIdx.x;
    int i4 = i * 4;
    const void* dbase = is64 ? (const void*)((const long long*)edge + E)
                             : (const void*)((const int*)edge + E);
    if (i4 + 3 < E) {
        int4 s = load4idx(edge, i, is64);
        int4 d = load4idx(dbase, i, is64);
        int4 r = ((const int4*)gcn_rank)[i];
        int o0 = __ldg(&gcn_off[d.x]);
        int o1 = __ldg(&gcn_off[d.y]);
        int o2 = __ldg(&gcn_off[d.z]);
        int o3 = __ldg(&gcn_off[d.w]);
        gcn_csrc[o0 + r.x] = s.x;
        gcn_csrc[o1 + r.y] = s.y;
        gcn_csrc[o2 + r.z] = s.z;
        gcn_csrc[o3 + r.w] = s.w;
    } else {
        for (int e = i4; e < E; e++) {
            int s, d;
            if (is64) {
                s = (int)((const long long*)edge)[e];
                d = (int)((const long long*)edge)[(size_t)E + e];
            } else {
                s = ((const int*)edge)[e];
                d = ((const int*)edge)[(size_t)E + e];
            }
            gcn_csrc[__ldg(&gcn_off[d]) + gcn_rank[e]] = s;
        }
    }
}

// ---------------- layer-1 transform (4 lanes/row, 128-thr blocks) -----------
__global__ __launch_bounds__(128) void k_mm1(const float* __restrict__ x,
                                             const float* __restrict__ W, int N) {
    __shared__ float sW[128 * 8];
    for (int t = threadIdx.x; t < 1024; t += 128) {
        int k = t >> 3, j = t & 7;
        sW[t] = (j < 6) ? W[k * 6 + j] : 0.0f;
    }
    __syncthreads();
    int g = blockIdx.x * 128 + threadIdx.x;
    int i = g >> 2;
    int q = g & 3;
    if (i >= N) return;
    const float4* xr = (const float4*)(x + (size_t)i * 128) + q * 8;
    float a[6];
#pragma unroll
    for (int j = 0; j < 6; j++) a[j] = 0.0f;
#pragma unroll
    for (int k4 = 0; k4 < 8; k4++) {
        float4 xv = xr[k4];
        const float* wp = &sW[(q * 8 + k4) * 32];
#pragma unroll
        for (int j = 0; j < 6; j++) {
            a[j] += xv.x * wp[j] + xv.y * wp[8 + j] + xv.z * wp[16 + j] + xv.w * wp[24 + j];
        }
    }
#pragma unroll
    for (int j = 0; j < 6; j++) {
        a[j] += __shfl_xor_sync(0xffffffffu, a[j], 1);
        a[j] += __shfl_xor_sync(0xffffffffu, a[j], 2);
    }
    if (q == 0) {
        float dinv = rsqrtf((float)(gcn_degi[i] + 1));   // +1: self loop
        gcn_degi[i] = 0;                                 // self-clean for next replay
        gcn_dinv[i] = dinv;
        float o[6] = { a[0] * dinv, a[1] * dinv, a[2] * dinv,
                       a[3] * dinv, a[4] * dinv, a[5] * dinv };
        gcn_bufA[i] = pack6(o);
    }
}

// --- fused CSR aggregation (4 threads/node, 128-thr blocks) + epilogue ------
template <bool APPLY_W>
__global__ __launch_bounds__(128) void k_csr(const uint4* __restrict__ vin,
                                             uint4* __restrict__ vout,
                                             const float* __restrict__ b,
                                             const float* __restrict__ W, int N) {
    __shared__ float sW[48];
    __shared__ float sb[6];
    if (threadIdx.x < 48) {
        int k = threadIdx.x >> 3, j = threadIdx.x & 7;
        sW[threadIdx.x] = (APPLY_W && j < 6) ? W[k * 6 + j] : 0.0f;
    }
    if (threadIdx.x < 6) sb[threadIdx.x] = b[threadIdx.x];
    __syncthreads();
    int g = blockIdx.x * 128 + threadIdx.x;
    int i = g >> 2;
    int q = g & 3;
    bool valid = (i < N);
    int pbase = 0, pend = 0;
    if (valid) { pbase = gcn_off[i] >> 2; pend = gcn_off[i + 1] >> 2; }

    float a[6];
    row_accum(vin, pbase, pend, q, a);

#pragma unroll
    for (int j = 0; j < 6; j++) {
        a[j] += __shfl_xor_sync(0xffffffffu, a[j], 1);
        a[j] += __shfl_xor_sync(0xffffffffu, a[j], 2);
    }
    if (!valid || q != 0) return;

    unpack_add(__ldg(&vin[i]), a);       // self loop
    float dinv = gcn_dinv[i];
    float h[6];
#pragma unroll
    for (int j = 0; j < 6; j++) h[j] = fmaxf(dinv * a[j] + sb[j], 0.0f);
    float o[6];
    if (APPLY_W) {
#pragma unroll
        for (int j = 0; j < 6; j++) {
            float s = 0.0f;
#pragma unroll
            for (int k = 0; k < 6; k++) s += h[k] * sW[k * 8 + j];
            o[j] = s * dinv;
        }
    } else {
#pragma unroll
        for (int j = 0; j < 6; j++) o[j] = h[j] * dinv;
    }
    vout[i] = pack6(o);
}

// ---------------- final: CSR agg (4t/node) + (agg @ Wf + bf) relu + pool ----
__global__ __launch_bounds__(128) void k_csr_final(const uint4* __restrict__ vin,
                                                   const float* __restrict__ Wf,
                                                   const float* __restrict__ bf, int N) {
    __shared__ float sW[60];
    __shared__ float sb[10];
    __shared__ float sp[NG * NC];
    for (int t = threadIdx.x; t < NG * NC; t += 128) sp[t] = 0.0f;
    if (threadIdx.x < 60) sW[threadIdx.x] = Wf[threadIdx.x];
    if (threadIdx.x < 10) sb[threadIdx.x] = bf[threadIdx.x];
    __syncthreads();
    int g = blockIdx.x * 128 + threadIdx.x;
    int i = g >> 2;
    int q = g & 3;
    bool valid = (i < N);
    int pbase = 0, pend = 0;
    if (valid) { pbase = gcn_off[i] >> 2; pend = gcn_off[i + 1] >> 2; }

    float a[6];
    row_accum(vin, pbase, pend, q, a);
#pragma unroll
    for (int j = 0; j < 6; j++) {
        a[j] += __shfl_xor_sync(0xffffffffu, a[j], 1);
        a[j] += __shfl_xor_sync(0xffffffffu, a[j], 2);
    }
    if (valid && q == 0) {
        unpack_add(__ldg(&vin[i]), a);
        float dinv = gcn_dinv[i];
#pragma unroll
        for (int j = 0; j < 6; j++) a[j] *= dinv;
        int bg = gcn_batch[i];
#pragma unroll
        for (int c = 0; c < 10; c++) {
            float s = sb[c];
#pragma unroll
            for (int j = 0; j < 6; j++) s += a[j] * sW[j * 10 + c];
            s = fmaxf(s, 0.0f);
            atomicAdd(&sp[bg * 10 + c], s);
        }
    }
    __syncthreads();
    int first = blockIdx.x * 32;           // 32 nodes per block (4 threads each)
    if (first >= N) return;
    int last = min(first + 31, N - 1);
    int bmin = gcn_batch[first], bmax = gcn_batch[last];   // batch sorted
    int cnt = (bmax - bmin + 1) * 10;
    for (int t = threadIdx.x; t < cnt; t += 128) {
        float v = sp[bmin * 10 + t];
        if (v != 0.0f) atomicAdd(&gcn_pool[bmin * 10 + t], v);
    }
}

// ------- mean + log_softmax; self-cleans pool/cnt for the next replay -------
__global__ void k_out(float* __restrict__ out) {
    int g = threadIdx.x;
    if (g < NG) {
        float cnt = fmaxf(gcn_cnt[g], 1.0f);
        float p[10];
        float m = -1e30f;
#pragma unroll
        for (int c = 0; c < 10; c++) {
            p[c] = gcn_pool[g * 10 + c] / cnt;
            m = fmaxf(m, p[c]);
        }
        float s = 0.0f;
#pragma unroll
        for (int c = 0; c < 10; c++) s += expf(p[c] - m);
        float l = logf(s);
#pragma unroll
        for (int c = 0; c < 10; c++) out[g * 10 + c] = p[c] - m - l;
    }
    __syncthreads();
    if (threadIdx.x < NG * NC) gcn_pool[threadIdx.x] = 0.0f;   // self-clean
    if (threadIdx.x < NG) gcn_cnt[threadIdx.x] = 0.0f;
}

// ---------------- launch ----------------
extern "C" void kernel_launch(void* const* d_in, const int* in_sizes, int n_in,
                              void* d_out, int out_size) {
    const float* x     = (const float*)d_in[0];
    const void*  edge  = d_in[1];
    const void*  batch = d_in[2];
    const float* W1 = (const float*)d_in[3];
    const float* b1 = (const float*)d_in[4];
    const float* W2 = (const float*)d_in[5];
    const float* b2 = (const float*)d_in[6];
    const float* W3 = (const float*)d_in[7];
    const float* b3 = (const float*)d_in[8];
    const float* W4 = (const float*)d_in[9];
    const float* b4 = (const float*)d_in[10];
    const float* W5 = (const float*)d_in[11];
    const float* b5 = (const float*)d_in[12];
    const float* W6 = (const float*)d_in[13];
    const float* b6 = (const float*)d_in[14];
    const float* Wf = (const float*)d_in[15];
    const float* bf = (const float*)d_in[16];

    int N = in_sizes[0] / 128;
    int E = in_sizes[1] / 2;
    float* out = (float*)d_out;

    int nb_n2 = (N + 127) / 128;
    int nb_e4 = ((E + 3) / 4 + 255) / 256;
    int nb_s  = (N + SCANB - 1) / SCANB;
    int nb_m4 = (4 * N + 127) / 128;   // 4 threads per node, 128-thr blocks

    void* pA; void* pB;
    cudaGetSymbolAddress(&pA, gcn_bufA);
    cudaGetSymbolAddress(&pB, gcn_bufB);
    uint4* A  = (uint4*)pA;
    uint4* Bv = (uint4*)pB;

    k_hist<<<nb_e4, 256>>>(edge, batch, N, E);
    k_scan1<<<nb_s, SCANB>>>(N);
    k_scan3<<<nb_n2, 128>>>(N, nb_s);   // fused scan2 + scan3 + pad
    k_fill<<<nb_e4, 256>>>(edge, N, E); // atomic-free scatter, 4 edges/thread

    k_mm1<<<nb_m4, 128>>>(x, W1, N);                        // -> A (g1); cleans degi
    k_csr<true><<<nb_m4, 128>>>(A, Bv, b1, W2, N);          // -> B (g2)
    k_csr<true><<<nb_m4, 128>>>(Bv, A, b2, W3, N);          // -> A (g3)
    k_csr<true><<<nb_m4, 128>>>(A, Bv, b3, W4, N);          // -> B (g4)
    k_csr<true><<<nb_m4, 128>>>(Bv, A, b4, W5, N);          // -> A (g5)
    k_csr<true><<<nb_m4, 128>>>(A, Bv, b5, W6, N);          // -> B (g6)
    k_csr<false><<<nb_m4, 128>>>(Bv, A, b6, nullptr, N);    // -> A (h6*dinv)
    k_csr_final<<<nb_m4, 128>>>(A, Wf, bf, N);
    k_out<<<1, NG * NC>>>(out);                             // cleans pool/cnt
}